// round 9
// baseline (speedup 1.0000x reference)
#include <cuda_runtime.h>
#include <cuda_fp16.h>
#include <math.h>
#include <stdint.h>

#define NN    8192
#define BB    16
#define CCH   128
#define MODES 64
#define KSPLIT 16

// ---------------- scratch ----------------
__device__ float  g_lutc[8192];                          // cos(2*pi*t/8192)
__device__ __half g_Th[128 * NN];                        // basis fp16 [j][n]
__device__ __half g_xh[(size_t)2048 * NN];               // x fp16 [r][n] (written by fwd gemm)
__device__ __half g_Ah[BB * 128 * 256];                  // inv A fp16 [b][o][k]
__device__ float  g_Pt[(size_t)KSPLIT * BB * 128 * 128]; // fwd partials [ks][b][j][i]
__device__ float  g_wT[MODES * CCH * CCH * 2];           // [m][o][i][re,im]

// ---------------- helpers ----------------
__device__ __forceinline__ uint32_t smem_u32(const void* p) {
    uint32_t a;
    asm("{ .reg .u64 t; cvta.to.shared.u64 t, %1; cvt.u32.u64 %0, t; }" : "=r"(a) : "l"(p));
    return a;
}
#define LDSM4(R, addr) \
    asm volatile("ldmatrix.sync.aligned.m8n8.x4.shared.b16 {%0,%1,%2,%3}, [%4];" \
        : "=r"((R)[0]), "=r"((R)[1]), "=r"((R)[2]), "=r"((R)[3]) : "r"(addr))
#define LDSM4T(R, addr) \
    asm volatile("ldmatrix.sync.aligned.m8n8.x4.trans.shared.b16 {%0,%1,%2,%3}, [%4];" \
        : "=r"((R)[0]), "=r"((R)[1]), "=r"((R)[2]), "=r"((R)[3]) : "r"(addr))
#define CP16(dst, src) \
    asm volatile("cp.async.cg.shared.global [%0], [%1], 16;" :: "r"(dst), "l"(src))
#define CPCOMMIT() asm volatile("cp.async.commit_group;" ::: "memory")
#define CPWAIT0()  asm volatile("cp.async.wait_group 0;" ::: "memory")
#define CPWAIT1()  asm volatile("cp.async.wait_group 1;" ::: "memory")

__device__ __forceinline__ void mma16816(float* c, const uint32_t* a, uint32_t b0, uint32_t b1) {
    asm volatile("mma.sync.aligned.m16n8k16.row.col.f32.f16.f16.f32 "
        "{%0,%1,%2,%3}, {%4,%5,%6,%7}, {%8,%9}, {%0,%1,%2,%3};"
        : "+f"(c[0]), "+f"(c[1]), "+f"(c[2]), "+f"(c[3])
        : "r"(a[0]), "r"(a[1]), "r"(a[2]), "r"(a[3]), "r"(b0), "r"(b1));
}
__device__ __forceinline__ uint32_t packh(__half a, __half b) {
    return (uint32_t)__half_as_ushort(a) | ((uint32_t)__half_as_ushort(b) << 16);
}
__device__ __forceinline__ uint2 cvt4(float4 v) {
    return make_uint2(packh(__float2half(v.x), __float2half(v.y)),
                      packh(__float2half(v.z), __float2half(v.w)));
}

// stage layouts (k-tile = 64, pitch 144 = 128+16)
// fwd: A [128 r][64 k] @0 ; B [128 j][64 k] @18432
#define FB_OFF 18432
#define FSZ    36864
#define FSMEM  (3 * FSZ)
// inv: A [128 o][64 k] @0 p144 ; B [64 k][128 n] @18432 p272
#define IB_OFF 18432
#define ISZ    36864
#define ISMEM  (3 * ISZ)

// ---------------------------------------------------------------------------
// Prep
// ---------------------------------------------------------------------------
__global__ void lut_fill() {
    int t = blockIdx.x * 256 + threadIdx.x;   // 8192
    float s, c;
    sincospif((float)t * (1.0f / 4096.0f), &s, &c);
    g_lutc[t] = c;
}

__global__ void fill_T() {
    int idx = blockIdx.x * 256 + threadIdx.x;   // 128*8192
    int j = idx >> 13;
    int n = idx & (NN - 1);
    int m = j & 63;
    int t = (m * n) & (NN - 1);
    if (j >= MODES) t = (t + 6144) & (NN - 1);   // sin = cos shifted
    g_Th[idx] = __float2half(g_lutc[t]);
}

__global__ void transpose_w(const float* __restrict__ w_spec) {
    int idx = blockIdx.x * 256 + threadIdx.x;   // 64*128*32
    int m  = idx & 63;
    int o  = (idx >> 6) & 127;
    int ib = idx >> 13;
    float2 v[4];
#pragma unroll
    for (int q = 0; q < 4; q++) {
        int i = ib * 4 + q;
        v[q] = *(const float2*)(w_spec + ((size_t)(i * CCH + o) * MODES + m) * 2);
    }
    float* dst = g_wT + ((size_t)(m * CCH + o) * CCH + ib * 4) * 2;
    *(float4*)(dst)     = make_float4(v[0].x, v[0].y, v[1].x, v[1].y);
    *(float4*)(dst + 4) = make_float4(v[2].x, v[2].y, v[3].x, v[3].y);
}

__global__ void prep_wc(const float* __restrict__ w_conv) {
    int idx = blockIdx.x * 256 + threadIdx.x;   // 16*128*128
    int b = idx >> 14;
    int o = (idx >> 7) & 127;
    int i = idx & 127;
    g_Ah[((size_t)(b * 128 + o)) * 256 + 128 + i] = __float2half(w_conv[o * 128 + i]);
}

// ---------------------------------------------------------------------------
// fwd compute: one 128x128x64 tile, single-pass fp16
// ---------------------------------------------------------------------------
__device__ __forceinline__ void compute_tile_f(float acc[2][8][4], uint32_t stg,
                                               int wm, int wn, int lane) {
    uint32_t n_off = (lane & 7) + ((lane >> 4) << 3);
    uint32_t kb = ((lane >> 3) & 1) * 16;
#pragma unroll
    for (int s16 = 0; s16 < 4; s16++) {
        uint32_t ah[2][4];
        uint32_t aaddr = stg + (uint32_t)(wm * 32 + (lane & 15)) * 144
                       + s16 * 32 + (lane >> 4) * 16;
        LDSM4(ah[0], aaddr);
        LDSM4(ah[1], aaddr + 16 * 144);
        uint32_t baddr = stg + FB_OFF + (uint32_t)(wn * 64 + n_off) * 144 + s16 * 32 + kb;
#pragma unroll
        for (int nb = 0; nb < 4; nb++) {
            uint32_t bh[4];
            LDSM4(bh, baddr + nb * 16 * 144);
#pragma unroll
            for (int half = 0; half < 2; half++) {
                int n = nb * 2 + half;
#pragma unroll
                for (int m = 0; m < 2; m++)
                    mma16816(acc[m][n], ah[m], bh[half * 2], bh[half * 2 + 1]);
            }
        }
    }
}

// inv compute: B via ldmatrix.trans on [k][n] layout (pitch 272)
__device__ __forceinline__ void compute_tile_i(float acc[2][8][4], uint32_t stg,
                                               int wm, int wn, int lane) {
#pragma unroll
    for (int s16 = 0; s16 < 4; s16++) {
        uint32_t ah[2][4];
        uint32_t aaddr = stg + (uint32_t)(wm * 32 + (lane & 15)) * 144
                       + s16 * 32 + (lane >> 4) * 16;
        LDSM4(ah[0], aaddr);
        LDSM4(ah[1], aaddr + 16 * 144);
        uint32_t baddr = stg + IB_OFF + (uint32_t)(s16 * 16 + (lane & 15)) * 272
                       + (uint32_t)(wn * 64) * 2 + (lane >> 4) * 16;
#pragma unroll
        for (int nb = 0; nb < 4; nb++) {
            uint32_t bh[4];
            LDSM4T(bh, baddr + nb * 32);
#pragma unroll
            for (int m = 0; m < 2; m++) {
                mma16816(acc[m][nb * 2],     ah[m], bh[0], bh[1]);
                mma16816(acc[m][nb * 2 + 1], ah[m], bh[2], bh[3]);
            }
        }
    }
}

// ---------------------------------------------------------------------------
// Forward GEMM (fused fp32->fp16 split of x):
//   Pt[ks][b][j][i] = sum_k x16[b*128+i][k] * T[j][k], also writes g_xh.
// grid (BB, KSPLIT), 256 threads, 2 CTAs/SM; K-chunk 512 = 8 k64-tiles
// ---------------------------------------------------------------------------
__global__ __launch_bounds__(256, 2) void gemm_fwd_mma(const float* __restrict__ x) {
    extern __shared__ char smem[];
    uint32_t sb = smem_u32(smem);
    int t = threadIdx.x, lane = t & 31, wid = t >> 5;
    int wm = wid & 3, wn = wid >> 2;
    int b = blockIdx.x, ks = blockIdx.y;
    int r0 = b * 128, kbase = ks * (NN / KSPLIT);
    const int NT = (NN / KSPLIT) / 64;   // 8

    float acc[2][8][4];
#pragma unroll
    for (int m = 0; m < 2; m++)
#pragma unroll
        for (int n = 0; n < 8; n++)
#pragma unroll
            for (int e = 0; e < 4; e++) acc[m][n][e] = 0.f;

    int arow = t >> 4, af4 = t & 15;   // A: 8 chunks of (row += 16), col f4

// load fp32 A tile into registers
#define FWD_LDA(T, VA) do { \
    int _k0 = kbase + (T) * 64; \
    _Pragma("unroll") \
    for (int q = 0; q < 8; q++) \
        VA[q] = *(const float4*)(x + (size_t)(r0 + arow + q * 16) * NN + _k0 + af4 * 4); \
} while (0)

// convert + store A tile to smem stage and to g_xh
#define FWD_STA(T, VA) do { \
    int _k0 = kbase + (T) * 64; \
    char* _st = smem + ((T) % 3) * FSZ; \
    _Pragma("unroll") \
    for (int q = 0; q < 8; q++) { \
        uint2 h = cvt4(VA[q]); \
        int row = arow + q * 16; \
        *(uint2*)(_st + row * 144 + af4 * 8) = h; \
        *(uint2*)(g_xh + (size_t)(r0 + row) * NN + _k0 + af4 * 4) = h; \
    } \
} while (0)

// async-load B (basis) tile
#define FWD_ISSUE_B(T) do { \
    int _k0 = kbase + (T) * 64; \
    uint32_t _st = sb + ((T) % 3) * FSZ; \
    _Pragma("unroll") \
    for (int q = 0; q < 4; q++) { \
        int c = t + q * 256, row = c >> 3, u = c & 7; \
        CP16(_st + FB_OFF + row * 144 + u * 16, g_Th + (size_t)row * NN + _k0 + u * 8); \
    } \
    CPCOMMIT(); \
} while (0)

    // prologue: stages 0 and 1
    {
        float4 va[8];
        FWD_LDA(0, va); FWD_ISSUE_B(0); FWD_STA(0, va);
        FWD_LDA(1, va); FWD_ISSUE_B(1); FWD_STA(1, va);
    }

#pragma unroll
    for (int tile = 0; tile < NT; tile++) {
        if (tile + 1 < NT) { CPWAIT1(); } else { CPWAIT0(); }
        __syncthreads();
        float4 va[8];
        bool hn = (tile + 2 < NT);
        if (hn) FWD_LDA(tile + 2, va);
        compute_tile_f(acc, sb + (tile % 3) * FSZ, wm, wn, lane);
        if (hn) { FWD_STA(tile + 2, va); FWD_ISSUE_B(tile + 2); }
    }
    __syncthreads();

    // epilogue: transpose through SMEM -> g_Pt[ks][b][j][i]
    float* ftile = (float*)smem;   // [j][132]
#pragma unroll
    for (int m = 0; m < 2; m++) {
        int r1 = wm * 32 + m * 16 + (lane >> 2);
#pragma unroll
        for (int n = 0; n < 8; n++) {
            int j = wn * 64 + n * 8 + (lane & 3) * 2;
            ftile[j * 132 + r1]           = acc[m][n][0];
            ftile[(j + 1) * 132 + r1]     = acc[m][n][1];
            ftile[j * 132 + r1 + 8]       = acc[m][n][2];
            ftile[(j + 1) * 132 + r1 + 8] = acc[m][n][3];
        }
    }
    __syncthreads();
    float* P = g_Pt + ((size_t)(ks * BB + b)) * 128 * 128;
#pragma unroll
    for (int w = 0; w < 16; w++) {
        int idx4 = t + w * 256;
        int j = idx4 >> 5, i4 = idx4 & 31;
        *(float4*)(P + (size_t)j * 128 + i4 * 4) = *(const float4*)&ftile[j * 132 + i4 * 4];
    }
}

// ---------------------------------------------------------------------------
// Mode mix (folds split-K reduce) -> fp16 coefficients into g_Ah [b][o][k<128]
// grid (64 m, 4 bg): each block handles 4 batches per w-row read
// ---------------------------------------------------------------------------
__global__ __launch_bounds__(256) void mode_mix() {
    int m = blockIdx.x, bg = blockIdx.y;
    int t = threadIdx.x;
    __shared__ float Fre[4][128], Fim[4][128];
#pragma unroll
    for (int q = 0; q < 2; q++) {
        int flat = t + q * 256;
        int bq = flat >> 7, i = flat & 127;
        int b = bg * 4 + bq;
        float sr = 0.f, si = 0.f;
#pragma unroll
        for (int ks = 0; ks < KSPLIT; ks++) {
            const float* Pb = g_Pt + ((size_t)(ks * BB + b)) * 128 * 128;
            sr += Pb[(size_t)m * 128 + i];
            si += Pb[(size_t)(64 + m) * 128 + i];
        }
        Fre[bq][i] = sr;
        Fim[bq][i] = -si;
    }
    __syncthreads();
    int o = t & 127, half = t >> 7;   // half handles batches half*2, half*2+1
    float aR[2] = {0.f, 0.f}, aI[2] = {0.f, 0.f};
    const float2* wrow = (const float2*)g_wT + (size_t)(m * CCH + o) * CCH;
#pragma unroll 8
    for (int i = 0; i < CCH; i++) {
        float2 w = wrow[i];
#pragma unroll
        for (int p = 0; p < 2; p++) {
            int bq = half * 2 + p;
            float fr = Fre[bq][i], fi = Fim[bq][i];
            aR[p] = fmaf(fr, w.x, fmaf(-fi, w.y, aR[p]));
            aI[p] = fmaf(fr, w.y, fmaf( fi, w.x, aI[p]));
        }
    }
    float sR = (m == 0) ? (1.0f / (float)NN) : (2.0f / (float)NN);
    float sI = (m == 0) ? 0.0f : (-2.0f / (float)NN);
#pragma unroll
    for (int p = 0; p < 2; p++) {
        int b = bg * 4 + half * 2 + p;
        size_t base = ((size_t)(b * 128 + o)) * 256;
        g_Ah[base + m]      = __float2half(aR[p] * sR);
        g_Ah[base + 64 + m] = __float2half(aI[p] * sI);
    }
}

// ---------------------------------------------------------------------------
// Inverse GEMM (fused iDFT + conv1x1 + bias + exact GELU)
// D[o][n] = sum_k A[o][k]*B[k][n], K=256 = 4 k64-tiles. grid (64 nt, 16 b)
// ---------------------------------------------------------------------------
__global__ __launch_bounds__(256, 2) void gemm_inv_mma(const float* __restrict__ b_conv,
                                                       float* __restrict__ out) {
    extern __shared__ char smem[];
    uint32_t sb = smem_u32(smem);
    int t = threadIdx.x, lane = t & 31, wid = t >> 5;
    int wm = wid & 3, wn = wid >> 2;
    int nt = blockIdx.x, b = blockIdx.y;
    int n0 = nt * 128;
    const int NT = 4;

    const __half* Ahb = g_Ah + (size_t)b * 32768;

    float acc[2][8][4];
#pragma unroll
    for (int m = 0; m < 2; m++)
#pragma unroll
        for (int n = 0; n < 8; n++)
#pragma unroll
            for (int e = 0; e < 4; e++) acc[m][n][e] = 0.f;

#define INV_ISSUE(T) do { \
    int _k0 = (T) * 64; \
    uint32_t _st = sb + ((T) % 3) * ISZ; \
    _Pragma("unroll") \
    for (int q = 0; q < 4; q++) { \
        int c = t + q * 256, row = c >> 3, u = c & 7; \
        CP16(_st + row * 144 + u * 16, Ahb + (size_t)row * 256 + _k0 + u * 8); \
    } \
    _Pragma("unroll") \
    for (int q = 0; q < 4; q++) { \
        int c = t + q * 256, kr = c >> 4, cc = c & 15; \
        int _k = _k0 + kr; \
        const __half* src = (_k < 128) ? (g_Th + (size_t)_k * NN + n0) \
                                       : (g_xh + (size_t)(b * 128 + _k - 128) * NN + n0); \
        CP16(_st + IB_OFF + kr * 272 + cc * 16, src + cc * 8); \
    } \
    CPCOMMIT(); \
} while (0)

    INV_ISSUE(0);
    INV_ISSUE(1);
#pragma unroll
    for (int tile = 0; tile < NT; tile++) {
        if (tile + 1 < NT) { CPWAIT1(); } else { CPWAIT0(); }
        __syncthreads();
        compute_tile_i(acc, sb + (tile % 3) * ISZ, wm, wn, lane);
        if (tile + 2 < NT) INV_ISSUE(tile + 2);
    }

    // epilogue: bias + exact GELU + store
#pragma unroll
    for (int m = 0; m < 2; m++) {
        int o0 = wm * 32 + m * 16 + (lane >> 2);
        float bias0 = b_conv[o0];
        float bias1 = b_conv[o0 + 8];
#pragma unroll
        for (int n = 0; n < 8; n++) {
            int ng = n0 + wn * 64 + n * 8 + (lane & 3) * 2;
            float v0 = acc[m][n][0] + bias0;
            float v1 = acc[m][n][1] + bias0;
            float v2 = acc[m][n][2] + bias1;
            float v3 = acc[m][n][3] + bias1;
            v0 = 0.5f * v0 * (1.0f + erff(v0 * 0.70710678118654752f));
            v1 = 0.5f * v1 * (1.0f + erff(v1 * 0.70710678118654752f));
            v2 = 0.5f * v2 * (1.0f + erff(v2 * 0.70710678118654752f));
            v3 = 0.5f * v3 * (1.0f + erff(v3 * 0.70710678118654752f));
            *(float2*)(out + ((size_t)(b * 128 + o0)) * NN + ng)     = make_float2(v0, v1);
            *(float2*)(out + ((size_t)(b * 128 + o0 + 8)) * NN + ng) = make_float2(v2, v3);
        }
    }
}

// ---------------------------------------------------------------------------
extern "C" void kernel_launch(void* const* d_in, const int* in_sizes, int n_in,
                              void* d_out, int out_size) {
    const float* x      = (const float*)d_in[0];
    const float* w_spec = (const float*)d_in[1];
    const float* w_conv = (const float*)d_in[2];
    const float* b_conv = (const float*)d_in[3];
    float* out = (float*)d_out;

    cudaFuncSetAttribute(gemm_fwd_mma, cudaFuncAttributeMaxDynamicSharedMemorySize, FSMEM);
    cudaFuncSetAttribute(gemm_inv_mma, cudaFuncAttributeMaxDynamicSharedMemorySize, ISMEM);

    lut_fill   <<<32, 256>>>();
    fill_T     <<<(128 * NN) / 256, 256>>>();
    transpose_w<<<(MODES * CCH * 32) / 256, 256>>>(w_spec);
    prep_wc    <<<(BB * 128 * 128) / 256, 256>>>(w_conv);

    gemm_fwd_mma<<<dim3(BB, KSPLIT), 256, FSMEM>>>(x);
    mode_mix    <<<dim3(MODES, 4), 256>>>();
    gemm_inv_mma<<<dim3(NN / 128, BB), 256, ISMEM>>>(b_conv, out);
}